// round 5
// baseline (speedup 1.0000x reference)
#include <cuda_runtime.h>

#define BB   256
#define TT   32

typedef unsigned long long ULL;

// Device-global scratch
__device__ float  g_E1[BB * TT * 128];    // [B][T][128] = enc @ W1e^T + b1
__device__ float  g_W1P[128 * 256];       // [j][k] W1 hc-part, row-major
__device__ float4 g_Whh4[32 * 512];       // [k4][r] : float4 = Whh[r][4k4..4k4+3]

__device__ __forceinline__ float fast_tanh(float x) {
    float y;
    asm("tanh.approx.f32 %0, %1;" : "=f"(y) : "f"(x));
    return y;
}
__device__ __forceinline__ ULL fma2(ULL a, ULL b, ULL c) {
    ULL d;
    asm("fma.rn.f32x2 %0, %1, %2, %3;" : "=l"(d) : "l"(a), "l"(b), "l"(c));
    return d;
}
__device__ __forceinline__ float2 unpack2(ULL v) {
    float2 r;
    asm("mov.b64 {%0, %1}, %2;" : "=f"(r.x), "=f"(r.y) : "l"(v));
    return r;
}
__device__ __forceinline__ ULL pack2(float a) {
    ULL v;
    asm("mov.b64 %0, {%1, %1};" : "=l"(v) : "f"(a));
    return v;
}

// ---------------------------------------------------------------------------
// Prep: E1 (blocks 0..255), Whh repack (256..263), W1 pack (264..271)
// ---------------------------------------------------------------------------
__global__ void __launch_bounds__(128)
prep_kernel(const float* __restrict__ enc,
            const float* __restrict__ W1,    // [128, 384] cols: [hc(256) | enc(128)]
            const float* __restrict__ b1,
            const float* __restrict__ Whh)   // [512,128]
{
    int bid = blockIdx.x;
    if (bid < BB) {
        __shared__ float enc_s[TT * 128];
        const float* eb = enc + bid * TT * 128;
        for (int i = threadIdx.x; i < TT * 128; i += blockDim.x)
            enc_s[i] = eb[i];
        __syncthreads();
        int h = threadIdx.x;
        float acc[TT];
        float bb = b1[h];
#pragma unroll
        for (int t = 0; t < TT; t++) acc[t] = bb;
        const float4* wrow = reinterpret_cast<const float4*>(W1 + h * 384 + 256);
#pragma unroll 2
        for (int k4 = 0; k4 < 32; k4++) {
            float4 w = wrow[k4];
#pragma unroll
            for (int t = 0; t < TT; t++) {
                float4 e = reinterpret_cast<const float4*>(enc_s + t * 128)[k4];
                acc[t] += w.x * e.x + w.y * e.y + w.z * e.z + w.w * e.w;
            }
        }
        float* outp = g_E1 + bid * TT * 128;
#pragma unroll
        for (int t = 0; t < TT; t++) outp[t * 128 + h] = acc[t];
    } else if (bid < 264) {
        int base = (bid - 256) * 8192;
        float* dst = reinterpret_cast<float*>(g_Whh4);
        for (int i = base + threadIdx.x; i < base + 8192; i += 128) {
            int k4 = i >> 11;
            int r  = (i >> 2) & 511;
            int m  = i & 3;
            dst[i] = Whh[r * 128 + (k4 << 2) + m];
        }
    } else {
        int jbase = (bid - 264) * 16;
        for (int idx = threadIdx.x; idx < 16 * 256; idx += 128) {
            int j = jbase + (idx >> 8), k = idx & 255;
            g_W1P[j * 256 + k] = W1[j * 384 + k];
        }
    }
}

// ---------------------------------------------------------------------------
// Main: 256 blocks x 256 threads, 1 batch/block, 2 CTAs per SM.
// ---------------------------------------------------------------------------
__global__ void __launch_bounds__(256, 2)
decoder_kernel(const float* __restrict__ enc,
               const float* __restrict__ yhist,
               const float* __restrict__ W2,
               const float* __restrict__ Wih,
               const float* __restrict__ bih,
               const float* __restrict__ bhh,
               const float* __restrict__ fcW,
               const float* __restrict__ fcb,
               const float* __restrict__ fcfW,
               const float* __restrict__ fcfb,
               float* __restrict__ out)
{
    extern __shared__ float sm[];
    float* sE1    = sm;                 // 4224 [t][132] padded rows
    float* sEnc   = sE1 + 4224;         // 4224 [t][132]
    float* sHb    = sEnc + 4224;        // 256  h[0..127], c[128..255]
    float* sgates = sHb + 256;          // 512
    float* sctx2  = sgates + 512;       // 512  float2[4][64] ctx partials
    float* sctxC  = sctx2 + 512;        // 128  combined ctx
    float* su     = sctxC + 128;        // 128
    float* sWih   = su + 128;           // 512
    float* sbias  = sWih + 512;         // 512
    float* sW2    = sbias + 512;        // 128
    float* sfcf   = sW2 + 128;          // 256
    float* sfc    = sfcf + 256;         // 132: fcW[0..128], [129]=fcb, [130]=fcfb
    float* sy     = sfc + 132;          // 32  yhist row
    float* slogS  = sy + 32;            // 32
    float* sY     = slogS + 32;         // 4

    const int tid  = threadIdx.x;
    const int lane = tid & 31;
    const int warp = tid >> 5;
    const int b    = blockIdx.x;

    // ---- persistent W1: thread (ja, kh) holds W1[ja][kh*128 .. +128)
    const int ja = ((warp & 7) << 4) | (lane & 15);
    const int kh = lane >> 4;
    ulonglong2 w1r[32];
    {
        const ulonglong2* src =
            reinterpret_cast<const ulonglong2*>(g_W1P + ja * 256 + kh * 128);
#pragma unroll
        for (int i = 0; i < 32; i++) w1r[i] = src[i];
    }

    // ---- load phase ----
    for (int i4 = tid; i4 < 1024; i4 += 256) {
        int t = i4 >> 5, c = i4 & 31;
        reinterpret_cast<float4*>(sE1)[t * 33 + c] =
            reinterpret_cast<const float4*>(g_E1 + (size_t)b * 4096)[i4];
        reinterpret_cast<float4*>(sEnc)[t * 33 + c] =
            reinterpret_cast<const float4*>(enc + (size_t)b * 4096)[i4];
    }
    for (int i = tid; i < 512; i += 256) {
        sWih[i]  = Wih[i];
        sbias[i] = bih[i] + bhh[i];
    }
    sHb[tid] = 0.f;
    if (tid < 128) sW2[tid]  = W2[tid];
    if (tid < 256) sfcf[tid] = fcfW[tid];
    if (tid < 132)
        sfc[tid] = (tid < 129) ? fcW[tid]
                 : (tid == 129) ? fcb[0]
                 : (tid == 130) ? fcfb[0] : 0.f;
    if (tid < 32) sy[tid] = yhist[b * TT + tid];
    __syncthreads();

    for (int step = 0; step < TT; step++) {
        // ---- A: u[ja] = hc . W1[ja]   (k-half per thread, shfl-16 reduce)
        {
            const ulonglong2* hv =
                reinterpret_cast<const ulonglong2*>(sHb) + kh * 32;
            ULL a0 = 0, a1 = 0, a2 = 0, a3 = 0;
#pragma unroll
            for (int i = 0; i < 32; i += 4) {
                ulonglong2 w0 = w1r[i],     h0 = hv[i];
                ulonglong2 w1 = w1r[i + 1], h1 = hv[i + 1];
                ulonglong2 w2 = w1r[i + 2], h2 = hv[i + 2];
                ulonglong2 w3 = w1r[i + 3], h3 = hv[i + 3];
                a0 = fma2(w0.x, h0.x, a0); a0 = fma2(w0.y, h0.y, a0);
                a1 = fma2(w1.x, h1.x, a1); a1 = fma2(w1.y, h1.y, a1);
                a2 = fma2(w2.x, h2.x, a2); a2 = fma2(w2.y, h2.y, a2);
                a3 = fma2(w3.x, h3.x, a3); a3 = fma2(w3.y, h3.y, a3);
            }
            float2 p0 = unpack2(a0), p1 = unpack2(a1);
            float2 p2 = unpack2(a2), p3 = unpack2(a3);
            float s = p0.x + p0.y + p1.x + p1.y + p2.x + p2.y + p3.x + p3.y;
            s += __shfl_xor_sync(0xffffffffu, s, 16);
            if (lane < 16) su[ja] = s;
        }
        __syncthreads();

        // ---- B: 32 logits; warp covers 4 t rows via 8-lane groups
        {
            int c8 = lane & 7;
            int p  = ((warp & 7) << 2) | (lane >> 3);
            const float4* e1r = reinterpret_cast<const float4*>(sE1 + p * 132);
            const float4* ur  = reinterpret_cast<const float4*>(su);
            const float4* wr  = reinterpret_cast<const float4*>(sW2);
            float s = 0.f;
#pragma unroll
            for (int c = 0; c < 4; c++) {
                int idx = c * 8 + c8;   // contiguous 128B per instruction
                float4 e = e1r[idx];
                float4 u = ur[idx];
                float4 w = wr[idx];
                s += fast_tanh(e.x + u.x) * w.x + fast_tanh(e.y + u.y) * w.y
                   + fast_tanh(e.z + u.z) * w.z + fast_tanh(e.w + u.w) * w.w;
            }
            s += __shfl_xor_sync(0xffffffffu, s, 1);
            s += __shfl_xor_sync(0xffffffffu, s, 2);
            s += __shfl_xor_sync(0xffffffffu, s, 4);
            if (c8 == 0) slogS[p] = s;
        }
        __syncthreads();

        // ---- C+D fused: per-warp redundant softmax in regs, then ctx partials
        {
            float l  = slogS[lane];
            float mx = l;
#pragma unroll
            for (int o = 16; o > 0; o >>= 1)
                mx = fmaxf(mx, __shfl_xor_sync(0xffffffffu, mx, o));
            float e   = __expf(l - mx);
            float sum = e;
#pragma unroll
            for (int o = 16; o > 0; o >>= 1)
                sum += __shfl_xor_sync(0xffffffffu, sum, o);
            float a = e / sum;   // lane holds attn weight for t = lane

            int tq = warp >> 1;                  // t-quarter 0..3
            int jp = ((warp & 1) << 5) | lane;   // j-pair 0..63
            const ULL* e2 = reinterpret_cast<const ULL*>(sEnc) + jp;
            ULL acc = 0;
#pragma unroll
            for (int i = 0; i < 8; i++) {
                int t = tq * 8 + i;
                ULL av = pack2(__shfl_sync(0xffffffffu, a, t));
                acc = fma2(av, e2[t * 66], acc);
            }
            reinterpret_cast<float2*>(sctx2)[tq * 64 + jp] = unpack2(acc);
        }
        __syncthreads();

        // ---- E (warp 0) + F (all threads)
        if (warp == 0) {
            float2 cA = make_float2(0.f, 0.f), cB = make_float2(0.f, 0.f);
#pragma unroll
            for (int tq = 0; tq < 4; tq++) {
                float2 pA = reinterpret_cast<const float2*>(sctx2)[tq * 64 + lane];
                float2 pB = reinterpret_cast<const float2*>(sctx2)[tq * 64 + lane + 32];
                cA.x += pA.x; cA.y += pA.y;
                cB.x += pB.x; cB.y += pB.y;
            }
            reinterpret_cast<float2*>(sctxC)[lane]      = cA;
            reinterpret_cast<float2*>(sctxC)[lane + 32] = cB;
            float s = cA.x * sfc[2 * lane] + cA.y * sfc[2 * lane + 1]
                    + cB.x * sfc[64 + 2 * lane] + cB.y * sfc[64 + 2 * lane + 1];
#pragma unroll
            for (int o = 16; o > 0; o >>= 1)
                s += __shfl_xor_sync(0xffffffffu, s, o);
            if (lane == 0)
                sY[0] = s + sy[step] * sfc[128] + sfc[129];
        }
        {
            // F: gates = Whh @ h ; thread owns rows {tid, tid+256}
            int r0 = tid, r1 = tid + 256;
            const ulonglong2* hp = reinterpret_cast<const ulonglong2*>(sHb);
            ULL a0 = 0, a1 = 0, b0 = 0, b1 = 0;
#pragma unroll
            for (int m = 0; m < 16; m++) {
                ulonglong2 w0 = __ldca(reinterpret_cast<const ulonglong2*>(
                                           g_Whh4 + m * 512 + r0));
                ulonglong2 w1 = __ldca(reinterpret_cast<const ulonglong2*>(
                                           g_Whh4 + m * 512 + r1));
                ulonglong2 h = hp[m];
                a0 = fma2(w0.x, h.x, a0); a0 = fma2(w0.y, h.y, a0);
                a1 = fma2(w1.x, h.x, a1); a1 = fma2(w1.y, h.y, a1);
            }
#pragma unroll
            for (int m = 16; m < 32; m++) {
                ulonglong2 w0 = __ldcg(reinterpret_cast<const ulonglong2*>(
                                           g_Whh4 + m * 512 + r0));
                ulonglong2 w1 = __ldcg(reinterpret_cast<const ulonglong2*>(
                                           g_Whh4 + m * 512 + r1));
                ulonglong2 h = hp[m];
                b0 = fma2(w0.x, h.x, b0); b0 = fma2(w0.y, h.y, b0);
                b1 = fma2(w1.x, h.x, b1); b1 = fma2(w1.y, h.y, b1);
            }
            float2 u0 = unpack2(a0), v0 = unpack2(b0);
            float2 u1 = unpack2(a1), v1 = unpack2(b1);
            sgates[r0] = u0.x + u0.y + v0.x + v0.y;
            sgates[r1] = u1.x + u1.y + v1.x + v1.y;
        }
        __syncthreads();

        // ---- G: LSTM cell (accurate activations)
        if (tid < 128) {
            int j = tid;
            float y  = sY[0];
            float g0 = sgates[j]       + sbias[j]       + y * sWih[j];
            float g1 = sgates[128 + j] + sbias[128 + j] + y * sWih[128 + j];
            float g2 = sgates[256 + j] + sbias[256 + j] + y * sWih[256 + j];
            float g3 = sgates[384 + j] + sbias[384 + j] + y * sWih[384 + j];
            float c_old = sHb[128 + j];
            float si = 1.f / (1.f + expf(-g0));
            float sf = 1.f / (1.f + expf(-g1));
            float so = 1.f / (1.f + expf(-g3));
            float cn = sf * c_old + si * tanhf(g2);
            float hn = so * tanhf(cn);
            sHb[128 + j] = cn;
            sHb[j]       = hn;
        }
        __syncthreads();
    }

    // ---- final: out[b] = [h, ctx] . fcfW + fcfb + y_history[b, T-1]
    if (warp == 0) {
        float4 hv = reinterpret_cast<const float4*>(sHb)[lane];
        float4 f1 = reinterpret_cast<const float4*>(sfcf)[lane];
        float4 cv = reinterpret_cast<const float4*>(sctxC)[lane];
        float4 f2 = reinterpret_cast<const float4*>(sfcf + 128)[lane];
        float s = hv.x * f1.x + hv.y * f1.y + hv.z * f1.z + hv.w * f1.w
                + cv.x * f2.x + cv.y * f2.y + cv.z * f2.z + cv.w * f2.w;
#pragma unroll
        for (int o = 16; o > 0; o >>= 1)
            s += __shfl_xor_sync(0xffffffffu, s, o);
        if (lane == 0)
            out[b] = s + sfc[130] + sy[31];
    }
}

// ---------------------------------------------------------------------------
extern "C" void kernel_launch(void* const* d_in, const int* in_sizes, int n_in,
                              void* d_out, int out_size)
{
    const float* enc  = (const float*)d_in[0];
    const float* yh   = (const float*)d_in[1];
    const float* W1   = (const float*)d_in[2];
    const float* b1   = (const float*)d_in[3];
    const float* W2   = (const float*)d_in[4];
    // d_in[5] = attn_b2 : cancels in softmax
    const float* Wih  = (const float*)d_in[6];
    const float* Whh  = (const float*)d_in[7];
    const float* bih  = (const float*)d_in[8];
    const float* bhh  = (const float*)d_in[9];
    const float* fcW  = (const float*)d_in[10];
    const float* fcb  = (const float*)d_in[11];
    const float* fcfW = (const float*)d_in[12];
    const float* fcfb = (const float*)d_in[13];
    float* out = (float*)d_out;

    const size_t smem_floats = 4224 + 4224 + 256 + 512 + 512 + 128 + 128
                             + 512 + 512 + 128 + 256 + 132 + 32 + 32 + 4;
    const size_t smem = smem_floats * sizeof(float);   // ~46.4 KB (x2 CTAs/SM)

    cudaFuncSetAttribute(decoder_kernel,
                         cudaFuncAttributeMaxDynamicSharedMemorySize, (int)smem);
    // 2 CTAs x 46KB smem ~= 93KB; leave ~135KB L1D for the pinned Whh half
    cudaFuncSetAttribute(decoder_kernel,
                         cudaFuncAttributePreferredSharedMemoryCarveout, 41);

    prep_kernel<<<272, 128>>>(enc, W1, b1, Whh);
    decoder_kernel<<<256, 256, smem>>>(enc, yh, W2, Wih, bih, bhh,
                                       fcW, fcb, fcfW, fcfb, out);
}

// round 6
// speedup vs baseline: 1.3488x; 1.3488x over previous
#include <cuda_runtime.h>

#define BB 256
#define TT 32

typedef unsigned long long ULL;

// Device-global scratch: repacked W_hh only
__device__ float4 g_Whh4[32 * 512];   // [k4][r] : float4 = Whh[r][4k4..4k4+3]

__device__ __forceinline__ float fast_tanh(float x) {
    float y;
    asm("tanh.approx.f32 %0, %1;" : "=f"(y) : "f"(x));
    return y;
}
__device__ __forceinline__ float fast_sig(float x) {
    return 0.5f + 0.5f * fast_tanh(0.5f * x);
}
__device__ __forceinline__ ULL fma2(ULL a, ULL b, ULL c) {
    ULL d;
    asm("fma.rn.f32x2 %0, %1, %2, %3;" : "=l"(d) : "l"(a), "l"(b), "l"(c));
    return d;
}
__device__ __forceinline__ float2 unpack2(ULL v) {
    float2 r;
    asm("mov.b64 {%0, %1}, %2;" : "=f"(r.x), "=f"(r.y) : "l"(v));
    return r;
}
__device__ __forceinline__ ULL pack2(float a) {
    ULL v;
    asm("mov.b64 %0, {%1, %1};" : "=l"(v) : "f"(a));
    return v;
}

// ---------------------------------------------------------------------------
// Tiny prep: repack Whh into [k4][r] float4 tiles (coalesced F loads)
// ---------------------------------------------------------------------------
__global__ void __launch_bounds__(128)
whh_prep(const float* __restrict__ Whh)   // [512,128]
{
    int base = blockIdx.x * 8192;
    float* dst = reinterpret_cast<float*>(g_Whh4);
    for (int i = base + threadIdx.x; i < base + 8192; i += 128) {
        int k4 = i >> 11;
        int r  = (i >> 2) & 511;
        int m  = i & 3;
        dst[i] = Whh[r * 128 + (k4 << 2) + m];
    }
}

// ---------------------------------------------------------------------------
// Main: 128 blocks x 512 threads, 2 batches/block. 4 barriers per step.
// ---------------------------------------------------------------------------
__global__ void __launch_bounds__(512, 1)
decoder_kernel(const float* __restrict__ enc,     // [B,32,128]
               const float* __restrict__ yhist,   // [B,32]
               const float* __restrict__ W1,      // [128,384] cols [h|c|enc]
               const float* __restrict__ b1,      // [128]
               const float* __restrict__ W2,      // [128]
               const float* __restrict__ Wih,     // [512]
               const float* __restrict__ bih,     // [512]
               const float* __restrict__ bhh,     // [512]
               const float* __restrict__ fcW,     // [129]
               const float* __restrict__ fcb,     // [1]
               const float* __restrict__ fcfW,    // [256]
               const float* __restrict__ fcfb,    // [1]
               float* __restrict__ out)           // [256]
{
    extern __shared__ float sm[];
    float* sEnc   = sm;                 // 8448 [64 rows][132]
    float* sE1    = sEnc + 8448;        // 8448 [64 rows][132]
    float* sHb    = sE1 + 8448;         // 512  [g][ h(128) c(128) ]
    float* sgates = sHb + 512;          // 1024 [g][512]
    float* su     = sgates + 1024;      // 256  [g][128]
    float* sctxC  = su + 256;           // 256  [g][128]
    float* sWih   = sctxC + 256;        // 512
    float* sbias  = sWih + 512;         // 512
    float* sW2    = sbias + 512;        // 128
    float* sfcf   = sW2 + 128;          // 256
    float* sfc    = sfcf + 256;         // 132: fcW[0..129), [129]=fcb, [130]=fcfb
    float* sy     = sfc + 132;          // 64  [g][32]
    float* slogS  = sy + 64;            // 64  [g][32]
    float* sEp    = slogS + 64;         // 16  [g][8] y_tilde partials

    const int tid  = threadIdx.x;
    const int lane = tid & 31;
    const int warp = tid >> 5;
    const int bp   = blockIdx.x * 2;

    // ---- load phase ----
    for (int i4 = tid; i4 < 2048; i4 += 512) {
        int r = i4 >> 5, c = i4 & 31;
        reinterpret_cast<float4*>(sEnc)[r * 33 + c] =
            reinterpret_cast<const float4*>(enc + (size_t)bp * 4096)[i4];
    }
    sWih[tid]  = Wih[tid];
    sbias[tid] = bih[tid] + bhh[tid];
    sHb[tid]   = 0.f;
    if (tid < 128) sW2[tid]  = W2[tid];
    if (tid < 256) sfcf[tid] = fcfW[tid];
    if (tid < 131)
        sfc[tid] = (tid < 129) ? fcW[tid] : (tid == 129) ? fcb[0] : fcfb[0];
    if (tid < 64) sy[tid] = yhist[(bp + (tid >> 5)) * 32 + (tid & 31)];
    __syncthreads();

    // ---- E1 = enc @ W1e^T + b1, in-CTA (once) ----
    {
        int h = tid & 127, rq = tid >> 7;   // 4 row-quarters x 16 rows
        float acc[16];
        float bb = b1[h];
#pragma unroll
        for (int rr = 0; rr < 16; rr++) acc[rr] = bb;
        const float4* wsrc = reinterpret_cast<const float4*>(W1 + h * 384 + 256);
#pragma unroll
        for (int ch = 0; ch < 4; ch++) {
            float4 w[8];
#pragma unroll
            for (int kk = 0; kk < 8; kk++) w[kk] = wsrc[ch * 8 + kk];
#pragma unroll
            for (int rr = 0; rr < 16; rr++) {
                const float4* ev = reinterpret_cast<const float4*>(
                    sEnc + (rq * 16 + rr) * 132) + ch * 8;
                float s = 0.f;
#pragma unroll
                for (int kk = 0; kk < 8; kk++) {
                    float4 e = ev[kk];
                    s += w[kk].x * e.x + w[kk].y * e.y
                       + w[kk].z * e.z + w[kk].w * e.w;
                }
                acc[rr] += s;
            }
        }
#pragma unroll
        for (int rr = 0; rr < 16; rr++)
            sE1[(rq * 16 + rr) * 132 + h] = acc[rr];
    }

    // ---- persistent A weights: thread (ja, qa) holds W1[ja][qa*64 .. +64)
    const int ja = (warp << 3) | (lane & 7);   // 0..127
    const int qa = lane >> 3;                  // k-quarter 0..3
    ulonglong2 w1r[16];
    {
        const ulonglong2* src =
            reinterpret_cast<const ulonglong2*>(W1 + ja * 384 + qa * 64);
#pragma unroll
        for (int i = 0; i < 16; i++) w1r[i] = src[i];
    }
    __syncthreads();

    for (int step = 0; step < TT; step++) {
        // ---- A: u[g][ja] = hc[g] . W1[ja]  (k-quarter per thread)
        {
            const ulonglong2* h0 =
                reinterpret_cast<const ulonglong2*>(sHb) + qa * 16;
            const ulonglong2* h1 =
                reinterpret_cast<const ulonglong2*>(sHb + 256) + qa * 16;
            ULL a0 = 0, a1 = 0, c0 = 0, c1 = 0;
#pragma unroll
            for (int i = 0; i < 16; i += 2) {
                ulonglong2 w  = w1r[i],     x  = h0[i],     y  = h1[i];
                a0 = fma2(w.x, x.x, a0);  a0 = fma2(w.y, x.y, a0);
                a1 = fma2(w.x, y.x, a1);  a1 = fma2(w.y, y.y, a1);
                ulonglong2 w2 = w1r[i + 1], x2 = h0[i + 1], y2 = h1[i + 1];
                c0 = fma2(w2.x, x2.x, c0); c0 = fma2(w2.y, x2.y, c0);
                c1 = fma2(w2.x, y2.x, c1); c1 = fma2(w2.y, y2.y, c1);
            }
            float2 p0 = unpack2(a0), p1 = unpack2(c0);
            float2 q0 = unpack2(a1), q1 = unpack2(c1);
            float s0 = p0.x + p0.y + p1.x + p1.y;
            float s1 = q0.x + q0.y + q1.x + q1.y;
            s0 += __shfl_xor_sync(0xffffffffu, s0, 8);
            s0 += __shfl_xor_sync(0xffffffffu, s0, 16);
            s1 += __shfl_xor_sync(0xffffffffu, s1, 8);
            s1 += __shfl_xor_sync(0xffffffffu, s1, 16);
            if (lane < 8) { su[ja] = s0; su[128 + ja] = s1; }
        }
        __syncthreads();

        // ---- B: 64 logits (2g x 32t); warp covers 4 rows via 8-lane groups
        {
            int c8 = lane & 7, pr = lane >> 3;
            int p  = (warp << 2) | pr;
            int pg = p >> 5, pt = p & 31;
            const float4* e1r = reinterpret_cast<const float4*>(
                sE1 + (pg * 32 + pt) * 132);
            const float4* ur  = reinterpret_cast<const float4*>(su) + pg * 32;
            const float4* wr  = reinterpret_cast<const float4*>(sW2);
            float s = 0.f;
#pragma unroll
            for (int c = 0; c < 4; c++) {
                int idx = c * 8 + c8;   // contiguous 128B per instruction
                float4 e = e1r[idx], u = ur[idx], w = wr[idx];
                s += fast_tanh(e.x + u.x) * w.x + fast_tanh(e.y + u.y) * w.y
                   + fast_tanh(e.z + u.z) * w.z + fast_tanh(e.w + u.w) * w.w;
            }
            s += __shfl_xor_sync(0xffffffffu, s, 1);
            s += __shfl_xor_sync(0xffffffffu, s, 2);
            s += __shfl_xor_sync(0xffffffffu, s, 4);
            if (c8 == 0) slogS[p] = s;
        }
        __syncthreads();

        // ---- C+D+E-partials (softmax in regs, ctx, y partials), then F
        {
            int g  = warp >> 3;          // warps 0-7: batch0, 8-15: batch1
            int wb = warp & 7;
            float l  = slogS[g * 32 + lane];
            float mx = l;
#pragma unroll
            for (int o = 16; o > 0; o >>= 1)
                mx = fmaxf(mx, __shfl_xor_sync(0xffffffffu, mx, o));
            float e   = __expf(l - mx);
            float sum = e;
#pragma unroll
            for (int o = 16; o > 0; o >>= 1)
                sum += __shfl_xor_sync(0xffffffffu, sum, o);
            float a = e / sum;           // lane's weight for t = lane

            int jp = (wb << 3) | (lane & 7);   // j-pair 0..63
            int ts = lane >> 3;                // t-slice 0..3
            const ULL* e2 = reinterpret_cast<const ULL*>(sEnc) + g * 2112 + jp;
            ULL acc = 0;
#pragma unroll
            for (int i = 0; i < 8; i++) {
                int t = ts * 8 + i;
                ULL av = pack2(__shfl_sync(0xffffffffu, a, t));
                acc = fma2(av, e2[t * 66], acc);
            }
            float2 v = unpack2(acc);
            v.x += __shfl_xor_sync(0xffffffffu, v.x, 8);
            v.y += __shfl_xor_sync(0xffffffffu, v.y, 8);
            v.x += __shfl_xor_sync(0xffffffffu, v.x, 16);
            v.y += __shfl_xor_sync(0xffffffffu, v.y, 16);
            float px = 0.f;
            if (ts == 0) {   // lanes 0..7 hold final ctx for their jp
                reinterpret_cast<float2*>(sctxC)[g * 64 + jp] = v;
                px = v.x * sfc[2 * jp] + v.y * sfc[2 * jp + 1];
            }
            px += __shfl_xor_sync(0xffffffffu, px, 1);
            px += __shfl_xor_sync(0xffffffffu, px, 2);
            px += __shfl_xor_sync(0xffffffffu, px, 4);
            if (lane == 0) sEp[g * 8 + wb] = px;
        }
        // ---- F: gates = Whh @ h, both batches; thread owns row r = tid.
        //      (independent of CD: reads h from last G, no barrier needed)
        {
            int r = tid;
            const ulonglong2* hp0 = reinterpret_cast<const ulonglong2*>(sHb);
            const ulonglong2* hp1 = reinterpret_cast<const ulonglong2*>(sHb + 256);
            ULL a0 = 0, a1 = 0, c0 = 0, c1 = 0;
#pragma unroll
            for (int m = 0; m < 16; m += 2) {
                ulonglong2 w0 = __ldca(reinterpret_cast<const ulonglong2*>(
                                           g_Whh4 + m * 512 + r));
                ulonglong2 w1 = __ldca(reinterpret_cast<const ulonglong2*>(
                                           g_Whh4 + (m + 1) * 512 + r));
                ulonglong2 hx0 = hp0[m],     hy0 = hp1[m];
                ulonglong2 hx1 = hp0[m + 1], hy1 = hp1[m + 1];
                a0 = fma2(w0.x, hx0.x, a0); a0 = fma2(w0.y, hx0.y, a0);
                a1 = fma2(w0.x, hy0.x, a1); a1 = fma2(w0.y, hy0.y, a1);
                c0 = fma2(w1.x, hx1.x, c0); c0 = fma2(w1.y, hx1.y, c0);
                c1 = fma2(w1.x, hy1.x, c1); c1 = fma2(w1.y, hy1.y, c1);
            }
#pragma unroll
            for (int m = 16; m < 32; m += 2) {
                ulonglong2 w0 = __ldcg(reinterpret_cast<const ulonglong2*>(
                                           g_Whh4 + m * 512 + r));
                ulonglong2 w1 = __ldcg(reinterpret_cast<const ulonglong2*>(
                                           g_Whh4 + (m + 1) * 512 + r));
                ulonglong2 hx0 = hp0[m],     hy0 = hp1[m];
                ulonglong2 hx1 = hp0[m + 1], hy1 = hp1[m + 1];
                a0 = fma2(w0.x, hx0.x, a0); a0 = fma2(w0.y, hx0.y, a0);
                a1 = fma2(w0.x, hy0.x, a1); a1 = fma2(w0.y, hy0.y, a1);
                c0 = fma2(w1.x, hx1.x, c0); c0 = fma2(w1.y, hx1.y, c0);
                c1 = fma2(w1.x, hy1.x, c1); c1 = fma2(w1.y, hy1.y, c1);
            }
            float2 u0 = unpack2(a0), u1 = unpack2(a1);
            float2 v0 = unpack2(c0), v1 = unpack2(c1);
            sgates[r]       = u0.x + u0.y + v0.x + v0.y;   // batch 0
            sgates[512 + r] = u1.x + u1.y + v1.x + v1.y;   // batch 1
        }
        __syncthreads();

        // ---- G: y_tilde combine + LSTM cell
        if (tid < 256) {
            int j = tid & 127, g = tid >> 7;
            const float* ep = sEp + g * 8;
            float y = ep[0] + ep[1] + ep[2] + ep[3]
                    + ep[4] + ep[5] + ep[6] + ep[7]
                    + sy[g * 32 + step] * sfc[128] + sfc[129];
            const float* gp = sgates + g * 512;
            float gv0 = gp[j]       + sbias[j]       + y * sWih[j];
            float gv1 = gp[128 + j] + sbias[128 + j] + y * sWih[128 + j];
            float gv2 = gp[256 + j] + sbias[256 + j] + y * sWih[256 + j];
            float gv3 = gp[384 + j] + sbias[384 + j] + y * sWih[384 + j];
            float c_old = sHb[g * 256 + 128 + j];
            float si = fast_sig(gv0);
            float sf = fast_sig(gv1);
            float so = fast_sig(gv3);
            float cn = sf * c_old + si * fast_tanh(gv2);
            float hn = so * fast_tanh(cn);
            sHb[g * 256 + 128 + j] = cn;
            sHb[g * 256 + j]       = hn;
        }
        __syncthreads();
    }

    // ---- final: out[b] = [h, ctx] . fcfW + fcfb + y_history[b, 31]
    if (warp < 2) {
        int g = warp;
        float4 hv = reinterpret_cast<const float4*>(sHb + g * 256)[lane];
        float4 f1 = reinterpret_cast<const float4*>(sfcf)[lane];
        float4 cv = reinterpret_cast<const float4*>(sctxC + g * 128)[lane];
        float4 f2 = reinterpret_cast<const float4*>(sfcf + 128)[lane];
        float s = hv.x * f1.x + hv.y * f1.y + hv.z * f1.z + hv.w * f1.w
                + cv.x * f2.x + cv.y * f2.y + cv.z * f2.z + cv.w * f2.w;
#pragma unroll
        for (int o = 16; o > 0; o >>= 1)
            s += __shfl_xor_sync(0xffffffffu, s, o);
        if (lane == 0)
            out[bp + g] = s + sfc[130] + sy[g * 32 + 31];
    }
}

// ---------------------------------------------------------------------------
extern "C" void kernel_launch(void* const* d_in, const int* in_sizes, int n_in,
                              void* d_out, int out_size)
{
    const float* enc  = (const float*)d_in[0];
    const float* yh   = (const float*)d_in[1];
    const float* W1   = (const float*)d_in[2];
    const float* b1   = (const float*)d_in[3];
    const float* W2   = (const float*)d_in[4];
    // d_in[5] = attn_b2 : constant shift, cancels in softmax
    const float* Wih  = (const float*)d_in[6];
    const float* Whh  = (const float*)d_in[7];
    const float* bih  = (const float*)d_in[8];
    const float* bhh  = (const float*)d_in[9];
    const float* fcW  = (const float*)d_in[10];
    const float* fcb  = (const float*)d_in[11];
    const float* fcfW = (const float*)d_in[12];
    const float* fcfb = (const float*)d_in[13];
    float* out = (float*)d_out;

    const size_t smem_floats = 8448 + 8448 + 512 + 1024 + 256 + 256
                             + 512 + 512 + 128 + 256 + 132 + 64 + 64 + 16;
    const size_t smem = smem_floats * sizeof(float);   // ~82.5 KB

    cudaFuncSetAttribute(decoder_kernel,
                         cudaFuncAttributeMaxDynamicSharedMemorySize, (int)smem);
    // small carveout -> ~145KB L1D for the ldca'd Whh half (128KB)
    cudaFuncSetAttribute(decoder_kernel,
                         cudaFuncAttributePreferredSharedMemoryCarveout, 38);

    whh_prep<<<8, 128>>>(Whh);
    decoder_kernel<<<128, 512, smem>>>(enc, yh, W1, b1, W2, Wih, bih, bhh,
                                       fcW, fcb, fcfW, fcfb, out);
}

// round 7
// speedup vs baseline: 1.5111x; 1.1204x over previous
#include <cuda_runtime.h>
#include <cuda_fp16.h>

#define BB 256
#define TT 32

typedef unsigned long long ULL;

// Device-global scratch: Whh converted to fp16, layout [m=16][r=512][8 halves]
// chunk m covers k = 8m..8m+7 of row r.
__device__ __half g_WhhH[16 * 512 * 8];

__device__ __forceinline__ float fast_tanh(float x) {
    float y;
    asm("tanh.approx.f32 %0, %1;" : "=f"(y) : "f"(x));
    return y;
}
__device__ __forceinline__ float fast_sig(float x) {
    return 0.5f + 0.5f * fast_tanh(0.5f * x);
}
__device__ __forceinline__ ULL fma2(ULL a, ULL b, ULL c) {
    ULL d;
    asm("fma.rn.f32x2 %0, %1, %2, %3;" : "=l"(d) : "l"(a), "l"(b), "l"(c));
    return d;
}
__device__ __forceinline__ float2 unpack2(ULL v) {
    float2 r;
    asm("mov.b64 {%0, %1}, %2;" : "=f"(r.x), "=f"(r.y) : "l"(v));
    return r;
}
__device__ __forceinline__ ULL pack2(float a) {
    ULL v;
    asm("mov.b64 %0, {%1, %1};" : "=l"(v) : "f"(a));
    return v;
}
__device__ __forceinline__ ULL pack2f(float2 f) {
    ULL v;
    asm("mov.b64 %0, {%1, %2};" : "=l"(v) : "f"(f.x), "f"(f.y));
    return v;
}
// uint holding 2 halves -> packed float2 (as ULL) for fma2
__device__ __forceinline__ ULL h2f2(unsigned u) {
    __half2 h = *reinterpret_cast<__half2*>(&u);
    return pack2f(__half22float2(h));
}

// ---------------------------------------------------------------------------
// Tiny prep: Whh fp32 -> fp16, layout [m][r][8]
// ---------------------------------------------------------------------------
__global__ void __launch_bounds__(128)
whh_prep(const float* __restrict__ Whh)   // [512,128]
{
    int base = blockIdx.x * 8192;
    for (int i = base + threadIdx.x; i < base + 8192; i += 128) {
        int j = i & 7;
        int r = (i >> 3) & 511;
        int m = i >> 12;
        g_WhhH[i] = __float2half(Whh[r * 128 + (m << 3) + j]);
    }
}

// ---------------------------------------------------------------------------
// Main: 128 blocks x 512 threads, 2 batches/block. 4 barriers per step.
// W_hh resident in SMEM as fp16 for all 32 steps.
// ---------------------------------------------------------------------------
__global__ void __launch_bounds__(512, 1)
decoder_kernel(const float* __restrict__ enc,     // [B,32,128]
               const float* __restrict__ yhist,   // [B,32]
               const float* __restrict__ W1,      // [128,384] cols [h|c|enc]
               const float* __restrict__ b1,      // [128]
               const float* __restrict__ W2,      // [128]
               const float* __restrict__ Wih,     // [512]
               const float* __restrict__ bih,     // [512]
               const float* __restrict__ bhh,     // [512]
               const float* __restrict__ fcW,     // [129]
               const float* __restrict__ fcb,     // [1]
               const float* __restrict__ fcfW,    // [256]
               const float* __restrict__ fcfb,    // [1]
               float* __restrict__ out)           // [256]
{
    extern __shared__ float sm[];
    float* sWhh   = sm;                 // 32768 float-slots = 128KB fp16 Whh
    float* sEnc   = sWhh + 32768;       // 8448 [64 rows][132]
    float* sE1    = sEnc + 8448;        // 8448 [64 rows][132]
    float* sHb    = sE1 + 8448;         // 512  [g][ h(128) c(128) ]
    float* sgates = sHb + 512;          // 1024 [g][512]
    float* su     = sgates + 1024;      // 256  [g][128]
    float* sctxC  = su + 256;           // 256  [g][128]
    float* sWih   = sctxC + 256;        // 512
    float* sbias  = sWih + 512;         // 512
    float* sW2    = sbias + 512;        // 128
    float* sfcf   = sW2 + 128;          // 256
    float* sfc    = sfcf + 256;         // 132: fcW[0..129), [129]=fcb, [130]=fcfb
    float* sy     = sfc + 132;          // 64  [g][32]
    float* slogS  = sy + 64;            // 64  [g][32]
    float* sEp    = slogS + 64;         // 16  [g][8] y_tilde partials

    const int tid  = threadIdx.x;
    const int lane = tid & 31;
    const int warp = tid >> 5;
    const int bp   = blockIdx.x * 2;

    // ---- load phase ----
    for (int i = tid; i < 8192; i += 512)
        reinterpret_cast<uint4*>(sWhh)[i] =
            reinterpret_cast<const uint4*>(g_WhhH)[i];
    for (int i4 = tid; i4 < 2048; i4 += 512) {
        int r = i4 >> 5, c = i4 & 31;
        reinterpret_cast<float4*>(sEnc)[r * 33 + c] =
            reinterpret_cast<const float4*>(enc + (size_t)bp * 4096)[i4];
    }
    sWih[tid]  = Wih[tid];
    sbias[tid] = bih[tid] + bhh[tid];
    sHb[tid]   = 0.f;
    if (tid < 128) sW2[tid]  = W2[tid];
    if (tid < 256) sfcf[tid] = fcfW[tid];
    if (tid < 131)
        sfc[tid] = (tid < 129) ? fcW[tid] : (tid == 129) ? fcb[0] : fcfb[0];
    if (tid < 64) sy[tid] = yhist[(bp + (tid >> 5)) * 32 + (tid & 31)];
    __syncthreads();

    // ---- E1 = enc @ W1e^T + b1, in-CTA (once) ----
    {
        int h = tid & 127, rq = tid >> 7;   // 4 row-quarters x 16 rows
        float acc[16];
        float bb = b1[h];
#pragma unroll
        for (int rr = 0; rr < 16; rr++) acc[rr] = bb;
        const float4* wsrc = reinterpret_cast<const float4*>(W1 + h * 384 + 256);
#pragma unroll
        for (int ch = 0; ch < 4; ch++) {
            float4 w[8];
#pragma unroll
            for (int kk = 0; kk < 8; kk++) w[kk] = wsrc[ch * 8 + kk];
#pragma unroll
            for (int rr = 0; rr < 16; rr++) {
                const float4* ev = reinterpret_cast<const float4*>(
                    sEnc + (rq * 16 + rr) * 132) + ch * 8;
                float s = 0.f;
#pragma unroll
                for (int kk = 0; kk < 8; kk++) {
                    float4 e = ev[kk];
                    s += w[kk].x * e.x + w[kk].y * e.y
                       + w[kk].z * e.z + w[kk].w * e.w;
                }
                acc[rr] += s;
            }
        }
#pragma unroll
        for (int rr = 0; rr < 16; rr++)
            sE1[(rq * 16 + rr) * 132 + h] = acc[rr];
    }

    // ---- persistent A weights: thread (ja, qa) holds W1[ja][qa*64 .. +64)
    const int ja = (warp << 3) | (lane & 7);   // 0..127
    const int qa = lane >> 3;                  // k-quarter 0..3
    ulonglong2 w1r[16];
    {
        const ulonglong2* src =
            reinterpret_cast<const ulonglong2*>(W1 + ja * 384 + qa * 64);
#pragma unroll
        for (int i = 0; i < 16; i++) w1r[i] = src[i];
    }
    __syncthreads();

    for (int step = 0; step < TT; step++) {
        // ---- A: u[g][ja] = hc[g] . W1[ja]  (k-quarter per thread)
        {
            const ulonglong2* h0 =
                reinterpret_cast<const ulonglong2*>(sHb) + qa * 16;
            const ulonglong2* h1 =
                reinterpret_cast<const ulonglong2*>(sHb + 256) + qa * 16;
            ULL a0 = 0, a1 = 0, c0 = 0, c1 = 0;
#pragma unroll
            for (int i = 0; i < 16; i += 2) {
                ulonglong2 w  = w1r[i],     x  = h0[i],     y  = h1[i];
                a0 = fma2(w.x, x.x, a0);  a0 = fma2(w.y, x.y, a0);
                a1 = fma2(w.x, y.x, a1);  a1 = fma2(w.y, y.y, a1);
                ulonglong2 w2 = w1r[i + 1], x2 = h0[i + 1], y2 = h1[i + 1];
                c0 = fma2(w2.x, x2.x, c0); c0 = fma2(w2.y, x2.y, c0);
                c1 = fma2(w2.x, y2.x, c1); c1 = fma2(w2.y, y2.y, c1);
            }
            float2 p0 = unpack2(a0), p1 = unpack2(c0);
            float2 q0 = unpack2(a1), q1 = unpack2(c1);
            float s0 = p0.x + p0.y + p1.x + p1.y;
            float s1 = q0.x + q0.y + q1.x + q1.y;
            s0 += __shfl_xor_sync(0xffffffffu, s0, 8);
            s0 += __shfl_xor_sync(0xffffffffu, s0, 16);
            s1 += __shfl_xor_sync(0xffffffffu, s1, 8);
            s1 += __shfl_xor_sync(0xffffffffu, s1, 16);
            if (lane < 8) { su[ja] = s0; su[128 + ja] = s1; }
        }
        __syncthreads();

        // ---- B: 64 logits (2g x 32t); warp covers 4 rows via 8-lane groups
        {
            int c8 = lane & 7, pr = lane >> 3;
            int p  = (warp << 2) | pr;
            int pg = p >> 5, pt = p & 31;
            const float4* e1r = reinterpret_cast<const float4*>(
                sE1 + (pg * 32 + pt) * 132);
            const float4* ur  = reinterpret_cast<const float4*>(su) + pg * 32;
            const float4* wr  = reinterpret_cast<const float4*>(sW2);
            float s = 0.f;
#pragma unroll
            for (int c = 0; c < 4; c++) {
                int idx = c * 8 + c8;   // contiguous 128B per instruction
                float4 e = e1r[idx], u = ur[idx], w = wr[idx];
                s += fast_tanh(e.x + u.x) * w.x + fast_tanh(e.y + u.y) * w.y
                   + fast_tanh(e.z + u.z) * w.z + fast_tanh(e.w + u.w) * w.w;
            }
            s += __shfl_xor_sync(0xffffffffu, s, 1);
            s += __shfl_xor_sync(0xffffffffu, s, 2);
            s += __shfl_xor_sync(0xffffffffu, s, 4);
            if (c8 == 0) slogS[p] = s;
        }
        __syncthreads();

        // ---- C+D+E-partials (softmax in regs, ctx, y partials), then F
        {
            int g  = warp >> 3;          // warps 0-7: batch0, 8-15: batch1
            int wb = warp & 7;
            float l  = slogS[g * 32 + lane];
            float mx = l;
#pragma unroll
            for (int o = 16; o > 0; o >>= 1)
                mx = fmaxf(mx, __shfl_xor_sync(0xffffffffu, mx, o));
            float e   = __expf(l - mx);
            float sum = e;
#pragma unroll
            for (int o = 16; o > 0; o >>= 1)
                sum += __shfl_xor_sync(0xffffffffu, sum, o);
            float a = e / sum;           // lane's weight for t = lane

            int jp = (wb << 3) | (lane & 7);   // j-pair 0..63
            int ts = lane >> 3;                // t-slice 0..3
            const ULL* e2 = reinterpret_cast<const ULL*>(sEnc) + g * 2112 + jp;
            ULL acc = 0;
#pragma unroll
            for (int i = 0; i < 8; i++) {
                int t = ts * 8 + i;
                ULL av = pack2(__shfl_sync(0xffffffffu, a, t));
                acc = fma2(av, e2[t * 66], acc);
            }
            float2 v = unpack2(acc);
            v.x += __shfl_xor_sync(0xffffffffu, v.x, 8);
            v.y += __shfl_xor_sync(0xffffffffu, v.y, 8);
            v.x += __shfl_xor_sync(0xffffffffu, v.x, 16);
            v.y += __shfl_xor_sync(0xffffffffu, v.y, 16);
            float px = 0.f;
            if (ts == 0) {   // lanes 0..7 hold final ctx for their jp
                reinterpret_cast<float2*>(sctxC)[g * 64 + jp] = v;
                px = v.x * sfc[2 * jp] + v.y * sfc[2 * jp + 1];
            }
            px += __shfl_xor_sync(0xffffffffu, px, 1);
            px += __shfl_xor_sync(0xffffffffu, px, 2);
            px += __shfl_xor_sync(0xffffffffu, px, 4);
            if (lane == 0) sEp[g * 8 + wb] = px;
        }
        // ---- F: gates = Whh @ h from SMEM-resident fp16 weights.
        //      (independent of CD: reads h from last G, no barrier needed)
        {
            int r = tid;
            const uint4* wp = reinterpret_cast<const uint4*>(sWhh) + r;
            const ulonglong2* hp0 = reinterpret_cast<const ulonglong2*>(sHb);
            const ulonglong2* hp1 = reinterpret_cast<const ulonglong2*>(sHb + 256);
            ULL a0 = 0, a1 = 0, c0 = 0, c1 = 0;
#pragma unroll
            for (int m = 0; m < 16; m++) {
                uint4 w = wp[m * 512];          // 8 halves: k = 8m..8m+7
                ulonglong2 x0 = hp0[2 * m], x1 = hp0[2 * m + 1];
                ulonglong2 y0 = hp1[2 * m], y1 = hp1[2 * m + 1];
                ULL w0 = h2f2(w.x), w1 = h2f2(w.y);
                ULL w2 = h2f2(w.z), w3 = h2f2(w.w);
                a0 = fma2(w0, x0.x, a0); a0 = fma2(w1, x0.y, a0);
                c0 = fma2(w2, x1.x, c0); c0 = fma2(w3, x1.y, c0);
                a1 = fma2(w0, y0.x, a1); a1 = fma2(w1, y0.y, a1);
                c1 = fma2(w2, y1.x, c1); c1 = fma2(w3, y1.y, c1);
            }
            float2 u0 = unpack2(a0), u1 = unpack2(a1);
            float2 v0 = unpack2(c0), v1 = unpack2(c1);
            sgates[r]       = u0.x + u0.y + v0.x + v0.y;   // batch 0
            sgates[512 + r] = u1.x + u1.y + v1.x + v1.y;   // batch 1
        }
        __syncthreads();

        // ---- G: y_tilde combine + LSTM cell
        if (tid < 256) {
            int j = tid & 127, g = tid >> 7;
            const float* ep = sEp + g * 8;
            float y = ep[0] + ep[1] + ep[2] + ep[3]
                    + ep[4] + ep[5] + ep[6] + ep[7]
                    + sy[g * 32 + step] * sfc[128] + sfc[129];
            const float* gp = sgates + g * 512;
            float gv0 = gp[j]       + sbias[j]       + y * sWih[j];
            float gv1 = gp[128 + j] + sbias[128 + j] + y * sWih[128 + j];
            float gv2 = gp[256 + j] + sbias[256 + j] + y * sWih[256 + j];
            float gv3 = gp[384 + j] + sbias[384 + j] + y * sWih[384 + j];
            float c_old = sHb[g * 256 + 128 + j];
            float si = fast_sig(gv0);
            float sf = fast_sig(gv1);
            float so = fast_sig(gv3);
            float cn = sf * c_old + si * fast_tanh(gv2);
            float hn = so * fast_tanh(cn);
            sHb[g * 256 + 128 + j] = cn;
            sHb[g * 256 + j]       = hn;
        }
        __syncthreads();
    }

    // ---- final: out[b] = [h, ctx] . fcfW + fcfb + y_history[b, 31]
    if (warp < 2) {
        int g = warp;
        float4 hv = reinterpret_cast<const float4*>(sHb + g * 256)[lane];
        float4 f1 = reinterpret_cast<const float4*>(sfcf)[lane];
        float4 cv = reinterpret_cast<const float4*>(sctxC + g * 128)[lane];
        float4 f2 = reinterpret_cast<const float4*>(sfcf + 128)[lane];
        float s = hv.x * f1.x + hv.y * f1.y + hv.z * f1.z + hv.w * f1.w
                + cv.x * f2.x + cv.y * f2.y + cv.z * f2.z + cv.w * f2.w;
#pragma unroll
        for (int o = 16; o > 0; o >>= 1)
            s += __shfl_xor_sync(0xffffffffu, s, o);
        if (lane == 0)
            out[bp + g] = s + sfc[130] + sy[g * 32 + 31];
    }
}

// ---------------------------------------------------------------------------
extern "C" void kernel_launch(void* const* d_in, const int* in_sizes, int n_in,
                              void* d_out, int out_size)
{
    const float* enc  = (const float*)d_in[0];
    const float* yh   = (const float*)d_in[1];
    const float* W1   = (const float*)d_in[2];
    const float* b1   = (const float*)d_in[3];
    const float* W2   = (const float*)d_in[4];
    // d_in[5] = attn_b2 : constant shift, cancels in softmax
    const float* Wih  = (const float*)d_in[6];
    const float* Whh  = (const float*)d_in[7];
    const float* bih  = (const float*)d_in[8];
    const float* bhh  = (const float*)d_in[9];
    const float* fcW  = (const float*)d_in[10];
    const float* fcb  = (const float*)d_in[11];
    const float* fcfW = (const float*)d_in[12];
    const float* fcfb = (const float*)d_in[13];
    float* out = (float*)d_out;

    const size_t smem_floats = 32768 + 8448 + 8448 + 512 + 1024 + 256 + 256
                             + 512 + 512 + 128 + 256 + 132 + 64 + 64 + 16;
    const size_t smem = smem_floats * sizeof(float);   // ~213.6 KB

    cudaFuncSetAttribute(decoder_kernel,
                         cudaFuncAttributeMaxDynamicSharedMemorySize, (int)smem);
    cudaFuncSetAttribute(decoder_kernel,
                         cudaFuncAttributePreferredSharedMemoryCarveout, 100);

    whh_prep<<<8, 128>>>(Whh);
    decoder_kernel<<<128, 512, smem>>>(enc, yh, W1, b1, W2, Wih, bih, bhh,
                                       fcW, fcb, fcfW, fcfb, out);
}

// round 8
// speedup vs baseline: 1.8131x; 1.1999x over previous
#include <cuda_runtime.h>
#include <cuda_fp16.h>

#define BB 256
#define TT 32

typedef unsigned long long ULL;

// Device-global scratch: Whh fp16, layout [m=16][r=512][8 halves]
// chunk m covers k = 8m..8m+7 of row r.
__device__ __half g_WhhH[16 * 512 * 8];

__device__ __forceinline__ float fast_tanh(float x) {
    float y;
    asm("tanh.approx.f32 %0, %1;" : "=f"(y) : "f"(x));
    return y;
}
__device__ __forceinline__ float fast_sig(float x) {
    return 0.5f + 0.5f * fast_tanh(0.5f * x);
}
__device__ __forceinline__ ULL fma2(ULL a, ULL b, ULL c) {
    ULL d;
    asm("fma.rn.f32x2 %0, %1, %2, %3;" : "=l"(d) : "l"(a), "l"(b), "l"(c));
    return d;
}
__device__ __forceinline__ float2 unpack2(ULL v) {
    float2 r;
    asm("mov.b64 {%0, %1}, %2;" : "=f"(r.x), "=f"(r.y) : "l"(v));
    return r;
}
__device__ __forceinline__ ULL pack2(float a) {
    ULL v;
    asm("mov.b64 %0, {%1, %1};" : "=l"(v) : "f"(a));
    return v;
}
__device__ __forceinline__ ULL pack2f(float2 f) {
    ULL v;
    asm("mov.b64 %0, {%1, %2};" : "=l"(v) : "f"(f.x), "f"(f.y));
    return v;
}
__device__ __forceinline__ ULL h2f2(unsigned u) {
    __half2 h = *reinterpret_cast<__half2*>(&u);
    return pack2f(__half22float2(h));
}

// padded hc layout: quarter q (64 floats) lives at q*68; batch stride 272.
#define HQ 68
#define HB 272

// ---------------------------------------------------------------------------
// Tiny prep: Whh fp32 -> fp16, layout [m][r][8]
// ---------------------------------------------------------------------------
__global__ void __launch_bounds__(128)
whh_prep(const float* __restrict__ Whh)   // [512,128]
{
    int base = blockIdx.x * 8192;
    for (int i = base + threadIdx.x; i < base + 8192; i += 128) {
        int j = i & 7;
        int r = (i >> 3) & 511;
        int m = i >> 12;
        g_WhhH[i] = __float2half(Whh[r * 128 + (m << 3) + j]);
    }
}

// ---------------------------------------------------------------------------
// Main: 128 blocks x 512 threads, 2 batches/block. 4 barriers per step.
// ---------------------------------------------------------------------------
__global__ void __launch_bounds__(512, 1)
decoder_kernel(const float* __restrict__ enc,     // [B,32,128]
               const float* __restrict__ yhist,   // [B,32]
               const float* __restrict__ W1,      // [128,384] cols [h|c|enc]
               const float* __restrict__ b1,      // [128]
               const float* __restrict__ W2,      // [128]
               const float* __restrict__ Wih,     // [512]
               const float* __restrict__ bih,     // [512]
               const float* __restrict__ bhh,     // [512]
               const float* __restrict__ fcW,     // [129]
               const float* __restrict__ fcb,     // [1]
               const float* __restrict__ fcfW,    // [256]
               const float* __restrict__ fcfb,    // [1]
               float* __restrict__ out)           // [256]
{
    extern __shared__ float sm[];
    float* sWhh  = sm;                 // 32768 float-slots = 128KB fp16 Whh
    float* sEnc  = sWhh + 32768;       // 8448 [64 rows][132]
    float* sE1   = sEnc + 8448;        // 8448 [64 rows][132]
    float* sHp   = sE1 + 8448;         // 552  padded hc: [g][q][68]
    float* sgp   = sHp + 552;          // 2048 [kh][g][512] gate partials
    float* su    = sgp + 2048;         // 256  [g][128]
    float* sctxC = su + 256;           // 256  [g][128]
    float* sWih  = sctxC + 256;        // 512
    float* sbias = sWih + 512;         // 512
    float* sW2   = sbias + 512;        // 128
    float* sfcf  = sW2 + 128;          // 256
    float* sfc   = sfcf + 256;         // 132: fcW[0..129), [129]=fcb, [130]=fcfb
    float* sy    = sfc + 132;          // 64  [g][32]
    float* slogS = sy + 64;            // 64
    float* sEp   = slogS + 64;         // 16  [g][8] y_tilde partials

    const int tid  = threadIdx.x;
    const int lane = tid & 31;
    const int warp = tid >> 5;
    const int bp   = blockIdx.x * 2;

    // ---- load phase ----
    for (int i = tid; i < 8192; i += 512)
        reinterpret_cast<uint4*>(sWhh)[i] =
            reinterpret_cast<const uint4*>(g_WhhH)[i];
    for (int i4 = tid; i4 < 2048; i4 += 512) {
        int r = i4 >> 5, c = i4 & 31;
        reinterpret_cast<float4*>(sEnc)[r * 33 + c] =
            reinterpret_cast<const float4*>(enc + (size_t)bp * 4096)[i4];
    }
    sWih[tid]  = Wih[tid];
    sbias[tid] = bih[tid] + bhh[tid];
    if (tid < 552) sHp[tid] = 0.f;
    if (tid < 128) sW2[tid]  = W2[tid];
    if (tid < 256) sfcf[tid] = fcfW[tid];
    if (tid < 131)
        sfc[tid] = (tid < 129) ? fcW[tid] : (tid == 129) ? fcb[0] : fcfb[0];
    if (tid < 64) sy[tid] = yhist[(bp + (tid >> 5)) * 32 + (tid & 31)];
    __syncthreads();

    // ---- E1 = enc @ W1e^T + b1, in-CTA (once) ----
    {
        int h = tid & 127, rq = tid >> 7;
        float acc[16];
        float bb = b1[h];
#pragma unroll
        for (int rr = 0; rr < 16; rr++) acc[rr] = bb;
        const float4* wsrc = reinterpret_cast<const float4*>(W1 + h * 384 + 256);
#pragma unroll
        for (int ch = 0; ch < 4; ch++) {
            float4 w[8];
#pragma unroll
            for (int kk = 0; kk < 8; kk++) w[kk] = wsrc[ch * 8 + kk];
#pragma unroll
            for (int rr = 0; rr < 16; rr++) {
                const float4* ev = reinterpret_cast<const float4*>(
                    sEnc + (rq * 16 + rr) * 132) + ch * 8;
                float s = 0.f;
#pragma unroll
                for (int kk = 0; kk < 8; kk++) {
                    float4 e = ev[kk];
                    s += w[kk].x * e.x + w[kk].y * e.y
                       + w[kk].z * e.z + w[kk].w * e.w;
                }
                acc[rr] += s;
            }
        }
#pragma unroll
        for (int rr = 0; rr < 16; rr++)
            sE1[(rq * 16 + rr) * 132 + h] = acc[rr];
    }

    // ---- persistent A weights: thread (ja, qa) holds W1[ja][qa*64 .. +64)
    const int ja = (warp << 3) | (lane & 7);   // 0..127
    const int qa = lane >> 3;                  // k-quarter 0..3
    ulonglong2 w1r[16];
    {
        const ulonglong2* src =
            reinterpret_cast<const ulonglong2*>(W1 + ja * 384 + qa * 64);
#pragma unroll
        for (int i = 0; i < 16; i++) w1r[i] = src[i];
    }

    // F coordinates: k-half per warp-half, 2 rows x 2 batches per thread
    const int khF = tid >> 8;          // warps 0-7: k[0,64), 8-15: k[64,128)
    const int rrF = tid & 255;
    __syncthreads();

    for (int step = 0; step < TT; step++) {
        // ---- A: u[g][ja] = hc[g] . W1[ja]  (padded quarters: conflict-free)
        {
            const ulonglong2* h0 =
                reinterpret_cast<const ulonglong2*>(sHp) + qa * 17;
            const ulonglong2* h1 =
                reinterpret_cast<const ulonglong2*>(sHp + HB) + qa * 17;
            ULL a0 = 0, a1 = 0, c0 = 0, c1 = 0;
#pragma unroll
            for (int i = 0; i < 16; i += 2) {
                ulonglong2 w  = w1r[i],     x  = h0[i],     y  = h1[i];
                a0 = fma2(w.x, x.x, a0);  a0 = fma2(w.y, x.y, a0);
                a1 = fma2(w.x, y.x, a1);  a1 = fma2(w.y, y.y, a1);
                ulonglong2 w2 = w1r[i + 1], x2 = h0[i + 1], y2 = h1[i + 1];
                c0 = fma2(w2.x, x2.x, c0); c0 = fma2(w2.y, x2.y, c0);
                c1 = fma2(w2.x, y2.x, c1); c1 = fma2(w2.y, y2.y, c1);
            }
            float2 p0 = unpack2(a0), p1 = unpack2(c0);
            float2 q0 = unpack2(a1), q1 = unpack2(c1);
            float s0 = p0.x + p0.y + p1.x + p1.y;
            float s1 = q0.x + q0.y + q1.x + q1.y;
            s0 += __shfl_xor_sync(0xffffffffu, s0, 8);
            s0 += __shfl_xor_sync(0xffffffffu, s0, 16);
            s1 += __shfl_xor_sync(0xffffffffu, s1, 8);
            s1 += __shfl_xor_sync(0xffffffffu, s1, 16);
            if (lane < 8) { su[ja] = s0; su[128 + ja] = s1; }
        }
        __syncthreads();

        // ---- B: 64 logits (2g x 32t); warp covers 4 rows via 8-lane groups
        {
            int c8 = lane & 7, pr = lane >> 3;
            int p  = (warp << 2) | pr;
            int pg = p >> 5, pt = p & 31;
            const float4* e1r = reinterpret_cast<const float4*>(
                sE1 + (pg * 32 + pt) * 132);
            const float4* ur  = reinterpret_cast<const float4*>(su) + pg * 32;
            const float4* wr  = reinterpret_cast<const float4*>(sW2);
            float s = 0.f;
#pragma unroll
            for (int c = 0; c < 4; c++) {
                int idx = c * 8 + c8;
                float4 e = e1r[idx], u = ur[idx], w = wr[idx];
                s += fast_tanh(e.x + u.x) * w.x + fast_tanh(e.y + u.y) * w.y
                   + fast_tanh(e.z + u.z) * w.z + fast_tanh(e.w + u.w) * w.w;
            }
            s += __shfl_xor_sync(0xffffffffu, s, 1);
            s += __shfl_xor_sync(0xffffffffu, s, 2);
            s += __shfl_xor_sync(0xffffffffu, s, 4);
            if (c8 == 0) slogS[p] = s;
        }
        __syncthreads();

        // ---- C+D+E-partials (softmax in regs, ctx, y partials)
        {
            int g  = warp >> 3;
            int wb = warp & 7;
            float l  = slogS[g * 32 + lane];
            float mx = l;
#pragma unroll
            for (int o = 16; o > 0; o >>= 1)
                mx = fmaxf(mx, __shfl_xor_sync(0xffffffffu, mx, o));
            float e   = __expf(l - mx);
            float sum = e;
#pragma unroll
            for (int o = 16; o > 0; o >>= 1)
                sum += __shfl_xor_sync(0xffffffffu, sum, o);
            float a = e / sum;

            int jp = (wb << 3) | (lane & 7);
            int ts = lane >> 3;
            const ULL* e2 = reinterpret_cast<const ULL*>(sEnc) + g * 2112 + jp;
            ULL acc = 0;
#pragma unroll
            for (int i = 0; i < 8; i++) {
                int t = ts * 8 + i;
                ULL av = pack2(__shfl_sync(0xffffffffu, a, t));
                acc = fma2(av, e2[t * 66], acc);
            }
            float2 v = unpack2(acc);
            v.x += __shfl_xor_sync(0xffffffffu, v.x, 8);
            v.y += __shfl_xor_sync(0xffffffffu, v.y, 8);
            v.x += __shfl_xor_sync(0xffffffffu, v.x, 16);
            v.y += __shfl_xor_sync(0xffffffffu, v.y, 16);
            float px = 0.f;
            if (ts == 0) {
                reinterpret_cast<float2*>(sctxC)[g * 64 + jp] = v;
                px = v.x * sfc[2 * jp] + v.y * sfc[2 * jp + 1];
            }
            px += __shfl_xor_sync(0xffffffffu, px, 1);
            px += __shfl_xor_sync(0xffffffffu, px, 2);
            px += __shfl_xor_sync(0xffffffffu, px, 4);
            if (lane == 0) sEp[g * 8 + wb] = px;
        }
        // ---- F: gate partials, k-half per warp-half, rows {rrF, rrF+256}.
        //      (independent of CD: reads h from last G, no barrier needed)
        {
            const uint4* wp = reinterpret_cast<const uint4*>(sWhh)
                            + (khF << 3) * 512 + rrF;
            // padded h chunk (g, i): 4 floats at hc-index 4i
            const ulonglong2* hp = reinterpret_cast<const ulonglong2*>(sHp);
            ULL a0 = 0, a1 = 0, c0 = 0, c1 = 0;   // (row0,b0)(row0,b1)(row1,b0)(row1,b1)
#pragma unroll
            for (int mm = 0; mm < 8; mm++) {
                int i0 = (khF << 4) | (mm << 1);     // chunk indices
                int i1 = i0 + 1;
                int s0i = ((i0 >> 4) * 17) + (i0 & 15);
                int s1i = ((i1 >> 4) * 17) + (i1 & 15);
                uint4 wA = wp[mm * 512];
                uint4 wB = wp[mm * 512 + 256];
                ulonglong2 x0 = hp[s0i],      x1 = hp[s1i];        // batch 0
                ulonglong2 y0 = hp[68 + s0i], y1 = hp[68 + s1i];   // batch 1
                ULL w0 = h2f2(wA.x), w1 = h2f2(wA.y);
                ULL w2 = h2f2(wA.z), w3 = h2f2(wA.w);
                a0 = fma2(w0, x0.x, a0); a0 = fma2(w1, x0.y, a0);
                a0 = fma2(w2, x1.x, a0); a0 = fma2(w3, x1.y, a0);
                a1 = fma2(w0, y0.x, a1); a1 = fma2(w1, y0.y, a1);
                a1 = fma2(w2, y1.x, a1); a1 = fma2(w3, y1.y, a1);
                ULL v0 = h2f2(wB.x), v1 = h2f2(wB.y);
                ULL v2 = h2f2(wB.z), v3 = h2f2(wB.w);
                c0 = fma2(v0, x0.x, c0); c0 = fma2(v1, x0.y, c0);
                c0 = fma2(v2, x1.x, c0); c0 = fma2(v3, x1.y, c0);
                c1 = fma2(v0, y0.x, c1); c1 = fma2(v1, y0.y, c1);
                c1 = fma2(v2, y1.x, c1); c1 = fma2(v3, y1.y, c1);
            }
            float2 u0 = unpack2(a0), u1 = unpack2(a1);
            float2 t0 = unpack2(c0), t1 = unpack2(c1);
            float* P = sgp + (khF << 10);
            P[rrF]             = u0.x + u0.y;   // row rrF, batch 0
            P[512 + rrF]       = u1.x + u1.y;   // row rrF, batch 1
            P[rrF + 256]       = t0.x + t0.y;   // row rrF+256, batch 0
            P[512 + rrF + 256] = t1.x + t1.y;   // row rrF+256, batch 1
        }
        __syncthreads();

        // ---- G: y_tilde combine + LSTM cell (writes padded h layout)
        if (tid < 256) {
            int j = tid & 127, g = tid >> 7;
            const float* ep = sEp + g * 8;
            float y = ep[0] + ep[1] + ep[2] + ep[3]
                    + ep[4] + ep[5] + ep[6] + ep[7]
                    + sy[g * 32 + step] * sfc[128] + sfc[129];
            float gv[4];
#pragma unroll
            for (int q = 0; q < 4; q++) {
                int r = q * 128 + j;
                gv[q] = sgp[g * 512 + r] + sgp[1024 + g * 512 + r]
                      + sbias[r] + y * sWih[r];
            }
            int hq = j >> 6, ho = j & 63;
            float* hb = sHp + g * HB;
            float c_old = hb[(2 + hq) * HQ + ho];
            float si = fast_sig(gv[0]);
            float sf = fast_sig(gv[1]);
            float so = fast_sig(gv[3]);
            float cn = sf * c_old + si * fast_tanh(gv[2]);
            float hn = so * fast_tanh(cn);
            hb[(2 + hq) * HQ + ho] = cn;
            hb[hq * HQ + ho]       = hn;
        }
        __syncthreads();
    }

    // ---- final: out[b] = [h, ctx] . fcfW + fcfb + y_history[b, 31]
    if (warp < 2) {
        int g = warp;
        float4 hv = reinterpret_cast<const float4*>(sHp + g * HB)
                        [(lane >> 4) * 17 + (lane & 15)];
        float4 f1 = reinterpret_cast<const float4*>(sfcf)[lane];
        float4 cv = reinterpret_cast<const float4*>(sctxC + g * 128)[lane];
        float4 f2 = reinterpret_cast<const float4*>(sfcf + 128)[lane];
        float s = hv.x * f1.x + hv.y * f1.y + hv.z * f1.z + hv.w * f1.w
                + cv.x * f2.x + cv.y * f2.y + cv.z * f2.z + cv.w * f2.w;
#pragma unroll
        for (int o = 16; o > 0; o >>= 1)
            s += __shfl_xor_sync(0xffffffffu, s, o);
        if (lane == 0)
            out[bp + g] = s + sfc[130] + sy[g * 32 + 31];
    }
}

// ---------------------------------------------------------------------------
extern "C" void kernel_launch(void* const* d_in, const int* in_sizes, int n_in,
                              void* d_out, int out_size)
{
    const float* enc  = (const float*)d_in[0];
    const float* yh   = (const float*)d_in[1];
    const float* W1   = (const float*)d_in[2];
    const float* b1   = (const float*)d_in[3];
    const float* W2   = (const float*)d_in[4];
    // d_in[5] = attn_b2 : constant shift, cancels in softmax
    const float* Wih  = (const float*)d_in[6];
    const float* Whh  = (const float*)d_in[7];
    const float* bih  = (const float*)d_in[8];
    const float* bhh  = (const float*)d_in[9];
    const float* fcW  = (const float*)d_in[10];
    const float* fcb  = (const float*)d_in[11];
    const float* fcfW = (const float*)d_in[12];
    const float* fcfb = (const float*)d_in[13];
    float* out = (float*)d_out;

    const size_t smem_floats = 32768 + 8448 + 8448 + 552 + 2048 + 256 + 256
                             + 512 + 512 + 128 + 256 + 132 + 64 + 64 + 16;
    const size_t smem = smem_floats * sizeof(float);   // ~212.7 KB

    cudaFuncSetAttribute(decoder_kernel,
                         cudaFuncAttributeMaxDynamicSharedMemorySize, (int)smem);
    cudaFuncSetAttribute(decoder_kernel,
                         cudaFuncAttributePreferredSharedMemoryCarveout, 100);

    whh_prep<<<8, 128>>>(Whh);
    decoder_kernel<<<128, 512, smem>>>(enc, yh, W1, b1, W2, Wih, bih, bhh,
                                       fcW, fcb, fcfW, fcfb, out);
}